// round 1
// baseline (speedup 1.0000x reference)
#include <cuda_runtime.h>

#define NN 100000
#define EE 1600000
#define FF 64
#define KK 6
#define NBLK_SCAN 98   /* ceil(NN/1024) */

// ---------------- scratch (static device globals; allocation-free) ----------
__device__ int   g_deg[NN];
__device__ float g_dinv[NN];
__device__ int   g_cnt[NN];
__device__ int   g_cursor[NN];
__device__ int   g_rowptr[NN + 1];
__device__ int   g_bsum[NBLK_SCAN];
__device__ int   g_boff[NBLK_SCAN];
__device__ int   g_srcs[EE];
__device__ float g_wts[EE];
__device__ float g_tx[5][(size_t)NN * FF];   // Tx1..Tx5

// ---------------- CSR build ------------------------------------------------
__global__ void zero_kernel() {
    int i = blockIdx.x * blockDim.x + threadIdx.x;
    if (i < NN) { g_deg[i] = 0; g_cnt[i] = 0; g_cursor[i] = 0; }
}

__global__ void hist_kernel(const int* __restrict__ ei) {
    int e = blockIdx.x * blockDim.x + threadIdx.x;
    if (e < EE) {
        atomicAdd(&g_deg[ei[e]], 1);        // out-degree by src (row)
        atomicAdd(&g_cnt[ei[EE + e]], 1);   // in-degree by dst (col)
    }
}

__global__ void dinv_kernel() {
    int i = blockIdx.x * blockDim.x + threadIdx.x;
    if (i < NN) {
        int d = g_deg[i];
        g_dinv[i] = (d > 0) ? rsqrtf((float)d) : 0.0f;
    }
}

__global__ void scanA_kernel() {
    __shared__ int sh[1024];
    int t   = threadIdx.x;
    int idx = blockIdx.x * 1024 + t;
    int v   = (idx < NN) ? g_cnt[idx] : 0;
    sh[t] = v;
    __syncthreads();
    for (int off = 1; off < 1024; off <<= 1) {
        int tv = (t >= off) ? sh[t - off] : 0;
        __syncthreads();
        sh[t] += tv;
        __syncthreads();
    }
    if (idx < NN) g_rowptr[idx] = sh[t] - v;   // exclusive within block
    if (t == 1023) g_bsum[blockIdx.x] = sh[1023];
}

__global__ void scanB_kernel() {
    if (threadIdx.x == 0) {
        int acc = 0;
        for (int i = 0; i < NBLK_SCAN; i++) { g_boff[i] = acc; acc += g_bsum[i]; }
        g_rowptr[NN] = acc;                    // == EE
    }
}

__global__ void scanC_kernel() {
    int idx = blockIdx.x * blockDim.x + threadIdx.x;
    if (idx < NN) g_rowptr[idx] += g_boff[idx >> 10];
}

__global__ void scatter_kernel(const int* __restrict__ ei) {
    int e = blockIdx.x * blockDim.x + threadIdx.x;
    if (e < EE) {
        int r = ei[e];
        int c = ei[EE + e];
        int pos = g_rowptr[c] + atomicAdd(&g_cursor[c], 1);
        g_srcs[pos] = r;
        g_wts[pos]  = -(g_dinv[r] * g_dinv[c]);
    }
}

// ---------------- propagation: out = alpha * (L_hat @ h) - sub -------------
// One warp per destination node; each lane owns 2 of the 64 features (float2).
__global__ void prop_kernel(const float* __restrict__ x,
                            int h_idx, int sub_idx, float alpha, int out_idx) {
    int gw   = (blockIdx.x * blockDim.x + threadIdx.x) >> 5;
    int lane = threadIdx.x & 31;
    if (gw >= NN) return;

    const float* h = (h_idx < 0) ? x : g_tx[h_idx];
    int s = g_rowptr[gw];
    int e = g_rowptr[gw + 1];

    float ax = 0.0f, ay = 0.0f;
    for (int i = s; i < e; i++) {
        int   sr = g_srcs[i];                       // lane-uniform broadcast
        float wv = g_wts[i];
        float2 hv = ((const float2*)(h + (size_t)sr * FF))[lane];  // 256B coalesced
        ax = fmaf(wv, hv.x, ax);
        ay = fmaf(wv, hv.y, ay);
    }
    float rx = alpha * ax, ry = alpha * ay;
    if (sub_idx > -2) {
        const float* sb = (sub_idx < 0) ? x : g_tx[sub_idx];
        float2 sv = ((const float2*)(sb + (size_t)gw * FF))[lane];
        rx -= sv.x; ry -= sv.y;
    }
    float2 r; r.x = rx; r.y = ry;
    ((float2*)(g_tx[out_idx] + (size_t)gw * FF))[lane] = r;
}

// ---------------- fused GEMM: out = relu(sum_k Tx_k @ W_k + b) -------------
// One thread per node row; all 6 W matrices in dynamic shared (broadcast LDS).
__global__ __launch_bounds__(256) void gemm_kernel(const float* __restrict__ x,
                                                   const float* __restrict__ W,
                                                   const float* __restrict__ b,
                                                   float* __restrict__ out) {
    extern __shared__ float sW[];   // KK*FF*FF floats = 96 KB
    for (int i = threadIdx.x; i < KK * FF * FF; i += blockDim.x) sW[i] = W[i];
    __syncthreads();

    int node = blockIdx.x * blockDim.x + threadIdx.x;
    if (node >= NN) return;

    float acc[FF];
#pragma unroll
    for (int j = 0; j < FF; j++) acc[j] = 0.0f;

#pragma unroll 1
    for (int k = 0; k < KK; k++) {
        const float* hb = (k == 0) ? x : g_tx[k - 1];
        const float4* hr = (const float4*)(hb + (size_t)node * FF);
        const float*  wk = sW + k * FF * FF;
#pragma unroll 1
        for (int i4 = 0; i4 < FF / 4; i4++) {
            float4 xv = __ldg(hr + i4);
#pragma unroll
            for (int ii = 0; ii < 4; ii++) {
                float xs = (ii == 0) ? xv.x : (ii == 1) ? xv.y : (ii == 2) ? xv.z : xv.w;
                const float4* wr = (const float4*)(wk + (i4 * 4 + ii) * FF);
#pragma unroll
                for (int j4 = 0; j4 < FF / 4; j4++) {
                    float4 wv = wr[j4];   // broadcast across warp (no bank conflict)
                    acc[j4 * 4 + 0] = fmaf(xs, wv.x, acc[j4 * 4 + 0]);
                    acc[j4 * 4 + 1] = fmaf(xs, wv.y, acc[j4 * 4 + 1]);
                    acc[j4 * 4 + 2] = fmaf(xs, wv.z, acc[j4 * 4 + 2]);
                    acc[j4 * 4 + 3] = fmaf(xs, wv.w, acc[j4 * 4 + 3]);
                }
            }
        }
    }

    float* orow = out + (size_t)node * FF;
#pragma unroll
    for (int j4 = 0; j4 < FF / 4; j4++) {
        float4 v;
        v.x = fmaxf(acc[j4 * 4 + 0] + __ldg(b + j4 * 4 + 0), 0.0f);
        v.y = fmaxf(acc[j4 * 4 + 1] + __ldg(b + j4 * 4 + 1), 0.0f);
        v.z = fmaxf(acc[j4 * 4 + 2] + __ldg(b + j4 * 4 + 2), 0.0f);
        v.w = fmaxf(acc[j4 * 4 + 3] + __ldg(b + j4 * 4 + 3), 0.0f);
        ((float4*)orow)[j4] = v;
    }
}

// ---------------- launch ----------------------------------------------------
extern "C" void kernel_launch(void* const* d_in, const int* in_sizes, int n_in,
                              void* d_out, int out_size) {
    const float* x  = (const float*)d_in[0];   // [N, 64]
    const int*   ei = (const int*)d_in[1];     // [2, E] row-major: src then dst
    const float* W  = (const float*)d_in[2];   // [6, 64, 64]
    const float* b  = (const float*)d_in[3];   // [64]
    float* out = (float*)d_out;                // [N, 64]

    cudaFuncSetAttribute(gemm_kernel, cudaFuncAttributeMaxDynamicSharedMemorySize,
                         KK * FF * FF * (int)sizeof(float));

    const int TB = 256;
    zero_kernel   <<<(NN + TB - 1) / TB, TB>>>();
    hist_kernel   <<<(EE + TB - 1) / TB, TB>>>(ei);
    dinv_kernel   <<<(NN + TB - 1) / TB, TB>>>();
    scanA_kernel  <<<NBLK_SCAN, 1024>>>();
    scanB_kernel  <<<1, 32>>>();
    scanC_kernel  <<<(NN + TB - 1) / TB, TB>>>();
    scatter_kernel<<<(EE + TB - 1) / TB, TB>>>(ei);

    int prop_blocks = (NN * 32 + TB - 1) / TB;   // warp per node
    prop_kernel<<<prop_blocks, TB>>>(x, -1, -2, 1.0f, 0);  // Tx1 = L x
    prop_kernel<<<prop_blocks, TB>>>(x,  0, -1, 2.0f, 1);  // Tx2 = 2 L Tx1 - x
    prop_kernel<<<prop_blocks, TB>>>(x,  1,  0, 2.0f, 2);  // Tx3
    prop_kernel<<<prop_blocks, TB>>>(x,  2,  1, 2.0f, 3);  // Tx4
    prop_kernel<<<prop_blocks, TB>>>(x,  3,  2, 2.0f, 4);  // Tx5

    gemm_kernel<<<(NN + TB - 1) / TB, TB, KK * FF * FF * (int)sizeof(float)>>>(x, W, b, out);
}